// round 1
// baseline (speedup 1.0000x reference)
#include <cuda_runtime.h>
#include <math.h>

// Problem constants
#define BATCH   64
#define SEQ     256
#define NTOK    16384      // BATCH*SEQ
#define VOCAB   16
#define DMODEL  512
#define DFF     2048
#define NLAYER  6
#define NHEAD   8
#define DHEAD   64
#define DLAT    256
#define SD      131072     // SEQ*DMODEL

// ---------------- scratch (static __device__ — allocation-free) ----------------
__device__ float g_X   [NTOK * DMODEL];        // activations (33.5 MB)
__device__ float g_QKV [NTOK * 3 * DMODEL];    // qkv projections (100 MB)
__device__ float g_O   [NTOK * DMODEL];        // attention output (33.5 MB)
__device__ float g_T   [NTOK * DMODEL];        // proj / ff2 output (33.5 MB)
__device__ float g_H   [NTOK * DFF];           // ffn hidden (134 MB)
__device__ float g_LP  [64 * BATCH * DLAT];    // latent split-K partials (4 MB)
__device__ float g_MEM [BATCH * DLAT];         // latent output

// ---------------- packed f32x2 helpers (sm_103a FFMA2 path) ----------------
__device__ __forceinline__ unsigned long long pack2(float lo, float hi) {
    unsigned long long r;
    asm("mov.b64 %0, {%1,%2};" : "=l"(r) : "f"(lo), "f"(hi));
    return r;
}
__device__ __forceinline__ void fma2(unsigned long long& d, unsigned long long a, unsigned long long b) {
    asm("fma.rn.f32x2 %0, %1, %2, %0;" : "+l"(d) : "l"(a), "l"(b));
}
__device__ __forceinline__ void mul2(unsigned long long& d, unsigned long long a) {
    asm("mul.rn.f32x2 %0, %0, %1;" : "+l"(d) : "l"(a));
}
__device__ __forceinline__ float2 unpack2(unsigned long long v) {
    float2 f;
    asm("mov.b64 {%0,%1}, %2;" : "=f"(f.x), "=f"(f.y) : "l"(v));
    return f;
}

__device__ __forceinline__ float warpSum(float v) {
    #pragma unroll
    for (int o = 16; o > 0; o >>= 1) v += __shfl_xor_sync(0xffffffffu, v, o);
    return v;
}

// ---------------- embedding + positional encoding ----------------
// X[t,d] = sum_v src[t,v]*emb_w[d,v] + emb_b[d] + pe(t%SEQ, d)
__global__ void embed_kernel(const float* __restrict__ src,
                             const float* __restrict__ ew,
                             const float* __restrict__ eb,
                             float* __restrict__ X) {
    __shared__ float sv[VOCAB];
    const int t   = blockIdx.x;
    const int tid = threadIdx.x;              // 128 threads
    if (tid < VOCAB) sv[tid] = src[(size_t)t * VOCAB + tid];
    __syncthreads();
    const int s = t & (SEQ - 1);
    const float c = 0.017988946f;             // log(10000)/512 (f32)
    #pragma unroll
    for (int r = 0; r < 4; r++) {
        const int d = tid + r * 128;
        float acc = eb[d];
        #pragma unroll
        for (int v = 0; v < VOCAB; v++) acc += sv[v] * ew[d * VOCAB + v];
        const int i2 = d & ~1;                // 2*(d/2)
        const float den = expf(-(float)i2 * c);
        const float arg = (float)s * den;
        const float pe = (d & 1) ? cosf(arg) : sinf(arg);
        X[(size_t)t * DMODEL + d] = acc + pe;
    }
}

// ---------------- tiled SGEMM: C[M,N] = A[M,K] @ W[N,K]^T + bias, opt ReLU ----
// BM=BN=128, BK=16, 256 threads, 8x8 per thread, f32x2 inner loop.
// Requires M%128==0, N%128==0, K%16==0.
template <int ACT>
__global__ __launch_bounds__(256, 2)
void gemm_bias(const float* __restrict__ A, const float* __restrict__ W,
               const float* __restrict__ bias, float* __restrict__ C,
               int M, int N, int K) {
    __shared__ float As[16][128];
    __shared__ float Ws[16][128];
    const int tid = threadIdx.x;
    const int tx  = tid & 15;      // N direction
    const int ty  = tid >> 4;      // M direction
    const int rowBase = blockIdx.y * 128;
    const int colBase = blockIdx.x * 128;
    const int lr = tid >> 2;           // 0..63
    const int lk = (tid & 3) * 4;      // 0,4,8,12

    unsigned long long acc[8][4];
    #pragma unroll
    for (int i = 0; i < 8; i++)
        #pragma unroll
        for (int j = 0; j < 4; j++) acc[i][j] = 0ULL;

    const float* Abase = A + (size_t)(rowBase + lr) * K;
    const float* Wbase = W + (size_t)(colBase + lr) * K;
    const size_t rstep = (size_t)64 * K;

    for (int k0 = 0; k0 < K; k0 += 16) {
        float4 a0 = *(const float4*)(Abase + k0 + lk);
        float4 a1 = *(const float4*)(Abase + rstep + k0 + lk);
        float4 w0 = *(const float4*)(Wbase + k0 + lk);
        float4 w1 = *(const float4*)(Wbase + rstep + k0 + lk);
        __syncthreads();
        As[lk + 0][lr] = a0.x; As[lk + 1][lr] = a0.y; As[lk + 2][lr] = a0.z; As[lk + 3][lr] = a0.w;
        As[lk + 0][lr + 64] = a1.x; As[lk + 1][lr + 64] = a1.y; As[lk + 2][lr + 64] = a1.z; As[lk + 3][lr + 64] = a1.w;
        Ws[lk + 0][lr] = w0.x; Ws[lk + 1][lr] = w0.y; Ws[lk + 2][lr] = w0.z; Ws[lk + 3][lr] = w0.w;
        Ws[lk + 0][lr + 64] = w1.x; Ws[lk + 1][lr + 64] = w1.y; Ws[lk + 2][lr + 64] = w1.z; Ws[lk + 3][lr + 64] = w1.w;
        __syncthreads();
        #pragma unroll
        for (int kk = 0; kk < 16; kk++) {
            float a[8];
            #pragma unroll
            for (int i = 0; i < 8; i++) a[i] = As[kk][ty * 8 + i];
            unsigned long long w2[4];
            const unsigned long long* wrow = (const unsigned long long*)&Ws[kk][0];
            #pragma unroll
            for (int j = 0; j < 4; j++) w2[j] = wrow[tx * 4 + j];
            #pragma unroll
            for (int i = 0; i < 8; i++) {
                unsigned long long ad = pack2(a[i], a[i]);
                #pragma unroll
                for (int j = 0; j < 4; j++) fma2(acc[i][j], ad, w2[j]);
            }
        }
    }

    #pragma unroll
    for (int i = 0; i < 8; i++) {
        const int r = rowBase + ty * 8 + i;
        #pragma unroll
        for (int j = 0; j < 4; j++) {
            float2 v = unpack2(acc[i][j]);
            const int c = colBase + tx * 8 + 2 * j;
            float o0 = v.x + __ldg(bias + c);
            float o1 = v.y + __ldg(bias + c + 1);
            if (ACT == 1) { o0 = fmaxf(o0, 0.f); o1 = fmaxf(o1, 0.f); }
            C[(size_t)r * N + c]     = o0;
            C[(size_t)r * N + c + 1] = o1;
        }
    }
}

// ---------------- fused attention (flash-style, one block per (b,h)) ----------
// QKV layout: [t, 1536] with q at [h*64+d], k at [512+h*64+d], v at [1024+h*64+d]
__global__ __launch_bounds__(256, 1)
void attention_kernel(const float* __restrict__ QKV, float* __restrict__ O) {
    extern __shared__ float sm[];
    float* Ks = sm;                 // [256][64]
    float* Vs = sm + SEQ * DHEAD;   // [256][64]
    const int h = blockIdx.x;
    const int b = blockIdx.y;
    const int tid = threadIdx.x;
    const size_t base = (size_t)b * SEQ * 1536;

    for (int idx = tid; idx < SEQ * DHEAD; idx += 256) {
        const int j = idx >> 6, d = idx & 63;
        const size_t rb = base + (size_t)j * 1536 + h * DHEAD + d;
        Ks[idx] = QKV[rb + 512];
        Vs[idx] = QKV[rb + 1024];
    }
    __syncthreads();

    // each thread owns q row tid
    unsigned long long q2[32];
    {
        const float* qp = QKV + base + (size_t)tid * 1536 + h * DHEAD;
        #pragma unroll
        for (int i = 0; i < 32; i++) q2[i] = pack2(qp[2 * i], qp[2 * i + 1]);
    }
    unsigned long long acc[32];
    #pragma unroll
    for (int i = 0; i < 32; i++) acc[i] = 0ULL;

    float m = -1e30f, lsum = 0.f;
    const unsigned long long* Ku = (const unsigned long long*)Ks;
    const unsigned long long* Vu = (const unsigned long long*)Vs;

    for (int j = 0; j < SEQ; j++) {
        unsigned long long d2 = 0ULL;
        #pragma unroll
        for (int i = 0; i < 32; i++) fma2(d2, q2[i], Ku[j * 32 + i]);
        float2 dp = unpack2(d2);
        const float sc = (dp.x + dp.y) * 0.125f;   // 1/sqrt(64)
        if (sc > m) {                               // rescale only on new max
            const float corr = expf(m - sc);
            lsum *= corr;
            unsigned long long c2 = pack2(corr, corr);
            #pragma unroll
            for (int i = 0; i < 32; i++) mul2(acc[i], c2);
            m = sc;
        }
        const float p = expf(sc - m);
        lsum += p;
        unsigned long long p2 = pack2(p, p);
        #pragma unroll
        for (int i = 0; i < 32; i++) fma2(acc[i], p2, Vu[j * 32 + i]);
    }

    const float invl = 1.f / lsum;
    float* op = O + ((size_t)b * SEQ + tid) * DMODEL + h * DHEAD;
    #pragma unroll
    for (int i = 0; i < 32; i++) {
        float2 v = unpack2(acc[i]);
        op[2 * i]     = v.x * invl;
        op[2 * i + 1] = v.y * invl;
    }
}

// ---------------- residual add + LayerNorm: X = LN(X + R)*g + b ---------------
__global__ void add_ln_kernel(float* __restrict__ X, const float* __restrict__ R,
                              const float* __restrict__ gamma, const float* __restrict__ beta) {
    const int t = blockIdx.x;
    const int tid = threadIdx.x;    // 256
    const size_t o = (size_t)t * DMODEL;
    const float y0 = X[o + tid] + R[o + tid];
    const float y1 = X[o + tid + 256] + R[o + tid + 256];
    float s  = y0 + y1;
    float sq = y0 * y0 + y1 * y1;

    __shared__ float sS[8], sQ[8];
    const float ws = warpSum(s), wq = warpSum(sq);
    const int w = tid >> 5, ln = tid & 31;
    if (ln == 0) { sS[w] = ws; sQ[w] = wq; }
    __syncthreads();
    float tS = 0.f, tQ = 0.f;
    #pragma unroll
    for (int i = 0; i < 8; i++) { tS += sS[i]; tQ += sQ[i]; }
    const float mean = tS * (1.f / DMODEL);
    const float var  = tQ * (1.f / DMODEL) - mean * mean;
    const float inv  = rsqrtf(var + 1e-5f);
    X[o + tid]       = (y0 - mean) * inv * gamma[tid]       + beta[tid];
    X[o + tid + 256] = (y1 - mean) * inv * gamma[tid + 256] + beta[tid + 256];
}

// ---------------- latent GEMM split-K: P[ks][b][n] partials ------------------
// mem[64,256] = X[64,131072] @ lat_w[256,131072]^T ; BM=64,BN=64,BK=16, KC=2048
__global__ __launch_bounds__(256, 2)
void latent_partial(const float* __restrict__ Xf, const float* __restrict__ Wl,
                    float* __restrict__ P) {
    __shared__ float As[16][64];
    __shared__ float Ws[16][64];
    const int tid = threadIdx.x;
    const int tx = tid & 15, ty = tid >> 4;
    const int nBase = blockIdx.x * 64;
    const int kBase = blockIdx.y * 2048;
    const int lr = tid >> 2;
    const int lk = (tid & 3) * 4;

    unsigned long long acc[4][2];
    #pragma unroll
    for (int i = 0; i < 4; i++) { acc[i][0] = 0ULL; acc[i][1] = 0ULL; }

    const float* Ab = Xf + (size_t)lr * SD + kBase;
    const float* Wb = Wl + (size_t)(nBase + lr) * SD + kBase;

    for (int k0 = 0; k0 < 2048; k0 += 16) {
        float4 a = *(const float4*)(Ab + k0 + lk);
        float4 w = *(const float4*)(Wb + k0 + lk);
        __syncthreads();
        As[lk + 0][lr] = a.x; As[lk + 1][lr] = a.y; As[lk + 2][lr] = a.z; As[lk + 3][lr] = a.w;
        Ws[lk + 0][lr] = w.x; Ws[lk + 1][lr] = w.y; Ws[lk + 2][lr] = w.z; Ws[lk + 3][lr] = w.w;
        __syncthreads();
        #pragma unroll
        for (int kk = 0; kk < 16; kk++) {
            float a4[4];
            #pragma unroll
            for (int i = 0; i < 4; i++) a4[i] = As[kk][ty * 4 + i];
            const unsigned long long* wrow = (const unsigned long long*)&Ws[kk][0];
            unsigned long long w2[2] = { wrow[tx * 2], wrow[tx * 2 + 1] };
            #pragma unroll
            for (int i = 0; i < 4; i++) {
                unsigned long long ad = pack2(a4[i], a4[i]);
                fma2(acc[i][0], ad, w2[0]);
                fma2(acc[i][1], ad, w2[1]);
            }
        }
    }
    #pragma unroll
    for (int i = 0; i < 4; i++) {
        const int bb = ty * 4 + i;
        #pragma unroll
        for (int j = 0; j < 2; j++) {
            float2 v = unpack2(acc[i][j]);
            const int n = nBase + tx * 4 + 2 * j;
            P[(size_t)blockIdx.y * (BATCH * DLAT) + bb * DLAT + n]     = v.x;
            P[(size_t)blockIdx.y * (BATCH * DLAT) + bb * DLAT + n + 1] = v.y;
        }
    }
}

__global__ void latent_reduce(const float* __restrict__ P, const float* __restrict__ lb,
                              float* __restrict__ mem) {
    const int idx = blockIdx.x * 256 + threadIdx.x;  // 16384
    float s = lb[idx & (DLAT - 1)];
    #pragma unroll 8
    for (int ks = 0; ks < 64; ks++) s += P[(size_t)ks * (BATCH * DLAT) + idx];
    mem[idx] = s;
}

// ---------------- head: pred[b] = sigmoid(mem[b]·head_w + head_b) ------------
__global__ void head_kernel(const float* __restrict__ mem, const float* __restrict__ hw,
                            const float* __restrict__ hb, float* __restrict__ out) {
    const int b = blockIdx.x;
    const int tid = threadIdx.x;  // 256
    float v = mem[b * DLAT + tid] * hw[tid];
    __shared__ float sS[8];
    const float ws = warpSum(v);
    if ((tid & 31) == 0) sS[tid >> 5] = ws;
    __syncthreads();
    if (tid == 0) {
        float t = 0.f;
        #pragma unroll
        for (int i = 0; i < 8; i++) t += sS[i];
        const float z = t + hb[0];
        out[b] = 1.f / (1.f + expf(-z));
    }
}

// ---------------- launch ----------------
extern "C" void kernel_launch(void* const* d_in, const int* in_sizes, int n_in,
                              void* d_out, int out_size) {
    const float* src    = (const float*)d_in[0];
    const float* emb_w  = (const float*)d_in[1];
    const float* emb_b  = (const float*)d_in[2];
    const float* qkv_w  = (const float*)d_in[3];
    const float* qkv_b  = (const float*)d_in[4];
    const float* out_w  = (const float*)d_in[5];
    const float* out_b  = (const float*)d_in[6];
    const float* ff1_w  = (const float*)d_in[7];
    const float* ff1_b  = (const float*)d_in[8];
    const float* ff2_w  = (const float*)d_in[9];
    const float* ff2_b  = (const float*)d_in[10];
    const float* ln1_g  = (const float*)d_in[11];
    const float* ln1_b  = (const float*)d_in[12];
    const float* ln2_g  = (const float*)d_in[13];
    const float* ln2_b  = (const float*)d_in[14];
    const float* lat_w  = (const float*)d_in[15];
    const float* lat_b  = (const float*)d_in[16];
    const float* head_w = (const float*)d_in[17];
    const float* head_b = (const float*)d_in[18];
    float* out = (float*)d_out;

    float *X, *QKV, *O, *Tb, *Hb, *P, *MEM;
    cudaGetSymbolAddress((void**)&X,   g_X);
    cudaGetSymbolAddress((void**)&QKV, g_QKV);
    cudaGetSymbolAddress((void**)&O,   g_O);
    cudaGetSymbolAddress((void**)&Tb,  g_T);
    cudaGetSymbolAddress((void**)&Hb,  g_H);
    cudaGetSymbolAddress((void**)&P,   g_LP);
    cudaGetSymbolAddress((void**)&MEM, g_MEM);

    cudaFuncSetAttribute(attention_kernel,
                         cudaFuncAttributeMaxDynamicSharedMemorySize, 131072);

    embed_kernel<<<NTOK, 128>>>(src, emb_w, emb_b, X);

    for (int l = 0; l < NLAYER; l++) {
        gemm_bias<0><<<dim3(12, 128), 256>>>(X, qkv_w + (size_t)l * 1536 * DMODEL,
                                             qkv_b + l * 1536, QKV, NTOK, 1536, DMODEL);
        attention_kernel<<<dim3(NHEAD, BATCH), 256, 131072>>>(QKV, O);
        gemm_bias<0><<<dim3(4, 128), 256>>>(O, out_w + (size_t)l * DMODEL * DMODEL,
                                            out_b + l * DMODEL, Tb, NTOK, DMODEL, DMODEL);
        add_ln_kernel<<<NTOK, 256>>>(X, Tb, ln1_g + l * DMODEL, ln1_b + l * DMODEL);
        gemm_bias<1><<<dim3(16, 128), 256>>>(X, ff1_w + (size_t)l * DFF * DMODEL,
                                             ff1_b + l * DFF, Hb, NTOK, DFF, DMODEL);
        gemm_bias<0><<<dim3(4, 128), 256>>>(Hb, ff2_w + (size_t)l * DMODEL * DFF,
                                            ff2_b + l * DMODEL, Tb, NTOK, DMODEL, DFF);
        add_ln_kernel<<<NTOK, 256>>>(X, Tb, ln2_g + l * DMODEL, ln2_b + l * DMODEL);
    }

    latent_partial<<<dim3(4, 64), 256>>>(X, lat_w, P);
    latent_reduce<<<64, 256>>>(P, lat_b, MEM);
    head_kernel<<<BATCH, 256>>>(MEM, head_w, head_b, out);
}

// round 3
// speedup vs baseline: 2.0090x; 2.0090x over previous
#include <cuda_runtime.h>
#include <cuda_bf16.h>
#include <math.h>
#include <stdint.h>

// Problem constants
#define BATCH   64
#define SEQ     256
#define NTOK    16384      // BATCH*SEQ
#define VOCAB   16
#define DMODEL  512
#define DFF     2048
#define NLAYER  6
#define NHEAD   8
#define DHEAD   64
#define DLAT    256
#define SD      131072     // SEQ*DMODEL

typedef __nv_bfloat16 bf16;

// ---------------- scratch (static __device__ — allocation-free) ----------------
__device__ float g_X   [NTOK * DMODEL];
__device__ float g_QKV [NTOK * 3 * DMODEL];
__device__ float g_T   [NTOK * DMODEL];
__device__ bf16  g_Xhi [NTOK * DMODEL];
__device__ bf16  g_Xlo [NTOK * DMODEL];
__device__ bf16  g_Ohi [NTOK * DMODEL];
__device__ bf16  g_Olo [NTOK * DMODEL];
__device__ bf16  g_Hhi [NTOK * DFF];
__device__ bf16  g_Hlo [NTOK * DFF];
__device__ bf16  g_Wqh [NLAYER * 3 * DMODEL * DMODEL];
__device__ bf16  g_Wql [NLAYER * 3 * DMODEL * DMODEL];
__device__ bf16  g_Woh [NLAYER * DMODEL * DMODEL];
__device__ bf16  g_Wol [NLAYER * DMODEL * DMODEL];
__device__ bf16  g_W1h [NLAYER * DFF * DMODEL];
__device__ bf16  g_W1l [NLAYER * DFF * DMODEL];
__device__ bf16  g_W2h [NLAYER * DMODEL * DFF];
__device__ bf16  g_W2l [NLAYER * DMODEL * DFF];
__device__ float g_LP  [64 * BATCH * DLAT];
__device__ float g_MEM [BATCH * DLAT];

// ---------------- helpers ----------------
__device__ __forceinline__ unsigned long long pack2(float lo, float hi) {
    unsigned long long r;
    asm("mov.b64 %0, {%1,%2};" : "=l"(r) : "f"(lo), "f"(hi));
    return r;
}
__device__ __forceinline__ void fma2(unsigned long long& d, unsigned long long a, unsigned long long b) {
    asm("fma.rn.f32x2 %0, %1, %2, %0;" : "+l"(d) : "l"(a), "l"(b));
}
__device__ __forceinline__ void mul2(unsigned long long& d, unsigned long long a) {
    asm("mul.rn.f32x2 %0, %0, %1;" : "+l"(d) : "l"(a));
}
__device__ __forceinline__ float2 unpack2(unsigned long long v) {
    float2 f;
    asm("mov.b64 {%0,%1}, %2;" : "=f"(f.x), "=f"(f.y) : "l"(v));
    return f;
}
__device__ __forceinline__ float warpSum(float v) {
    #pragma unroll
    for (int o = 16; o > 0; o >>= 1) v += __shfl_xor_sync(0xffffffffu, v, o);
    return v;
}
__device__ __forceinline__ uint32_t smem_u32(const void* p) {
    uint32_t a;
    asm("{ .reg .u64 t; cvta.to.shared.u64 t, %1; cvt.u32.u64 %0, t; }" : "=r"(a) : "l"(p));
    return a;
}

// ---------------- mma.sync / ldmatrix / cp.async wrappers --------------------
__device__ __forceinline__ void ldmx4(uint32_t* r, uint32_t addr) {
    asm volatile("ldmatrix.sync.aligned.m8n8.x4.shared.b16 {%0,%1,%2,%3}, [%4];"
        : "=r"(r[0]), "=r"(r[1]), "=r"(r[2]), "=r"(r[3]) : "r"(addr));
}
__device__ __forceinline__ void ldmx2(uint32_t* r, uint32_t addr) {
    asm volatile("ldmatrix.sync.aligned.m8n8.x2.shared.b16 {%0,%1}, [%2];"
        : "=r"(r[0]), "=r"(r[1]) : "r"(addr));
}
__device__ __forceinline__ void mma_bf16(float* d, const uint32_t* a, const uint32_t* b) {
    asm volatile("mma.sync.aligned.m16n8k16.row.col.f32.bf16.bf16.f32 "
        "{%0,%1,%2,%3}, {%4,%5,%6,%7}, {%8,%9}, {%0,%1,%2,%3};"
        : "+f"(d[0]), "+f"(d[1]), "+f"(d[2]), "+f"(d[3])
        : "r"(a[0]), "r"(a[1]), "r"(a[2]), "r"(a[3]), "r"(b[0]), "r"(b[1]));
}
__device__ __forceinline__ void cp_async16(uint32_t saddr, const void* gaddr) {
    asm volatile("cp.async.cg.shared.global [%0], [%1], 16;" :: "r"(saddr), "l"(gaddr));
}
__device__ __forceinline__ void cp_commit() {
    asm volatile("cp.async.commit_group;");
}
template <int N>
__device__ __forceinline__ void cp_wait() {
    asm volatile("cp.async.wait_group %0;" :: "n"(N));
}

// ---------------- weight hi/lo split ----------------
__global__ void split_kernel(const float* __restrict__ in, bf16* __restrict__ hi,
                             bf16* __restrict__ lo, int n) {
    const int i = blockIdx.x * 256 + threadIdx.x;
    if (i < n) {
        const float x = in[i];
        const bf16 h = __float2bfloat16(x);
        hi[i] = h;
        lo[i] = __float2bfloat16(x - __bfloat162float(h));
    }
}

// ---------------- embedding + posenc (+ hi/lo split) ----------------
__global__ void embed_kernel(const float* __restrict__ src,
                             const float* __restrict__ ew,
                             const float* __restrict__ eb,
                             float* __restrict__ X,
                             bf16* __restrict__ Xhi, bf16* __restrict__ Xlo) {
    __shared__ float sv[VOCAB];
    const int t   = blockIdx.x;
    const int tid = threadIdx.x;              // 128
    if (tid < VOCAB) sv[tid] = src[(size_t)t * VOCAB + tid];
    __syncthreads();
    const int s = t & (SEQ - 1);
    const float c = 0.017988946f;             // log(10000)/512
    #pragma unroll
    for (int r = 0; r < 4; r++) {
        const int d = tid + r * 128;
        float acc = eb[d];
        #pragma unroll
        for (int v = 0; v < VOCAB; v++) acc += sv[v] * ew[d * VOCAB + v];
        const int i2 = d & ~1;
        const float den = expf(-(float)i2 * c);
        const float arg = (float)s * den;
        const float pe = (d & 1) ? cosf(arg) : sinf(arg);
        const float y = acc + pe;
        const size_t o = (size_t)t * DMODEL + d;
        X[o] = y;
        const bf16 h = __float2bfloat16(y);
        Xhi[o] = h;
        Xlo[o] = __float2bfloat16(y - __bfloat162float(h));
    }
}

// ---------------- HMMA GEMM: C[M,N] = (Ahi+Alo)[M,K] @ (Whi+Wlo)[N,K]^T + bias
// 3-term bf16 split (hi*hi + hi*lo + lo*hi), fp32 accumulators.
// 128x128x32 CTA tile, 8 warps (2Mx4N), cp.async double buffer, ldmatrix.
// Smem buffer layout (per 32KB buffer): Ahi[8K] Alo[8K] Whi[8K] Wlo[8K],
// each matrix: 128 rows x 64B, 16B chunks XOR-swizzled: c ^= (r>>1)&3.
// OUT=0: fp32 C + bias.  OUT=2: relu(C+bias) split to Chi/Clo bf16.
template <int OUT>
__global__ __launch_bounds__(256, 1)
void gemm_tc(const bf16* __restrict__ Ahi, const bf16* __restrict__ Alo,
             const bf16* __restrict__ Whi, const bf16* __restrict__ Wlo,
             const float* __restrict__ bias,
             float* __restrict__ C, bf16* __restrict__ Chi, bf16* __restrict__ Clo,
             int M, int N, int K) {
    extern __shared__ char smraw[];
    const uint32_t sbase = smem_u32(smraw);
    const int tid  = threadIdx.x;
    const int lane = tid & 31;
    const int wid  = tid >> 5;
    const int wm   = wid >> 2;          // 0..1
    const int wn   = wid & 3;           // 0..3
    const int mBase = blockIdx.y * 128;
    const int nBase = blockIdx.x * 128;

    // per-lane ldmatrix base offsets (relative to matrix start), per k-step
    uint32_t aA[2], aB[2];
    {
        const int rowA = wm * 64 + (lane & 7) + ((lane >> 3) & 1) * 8;
        const int rowB = wn * 32 + (lane & 7);
        #pragma unroll
        for (int ks = 0; ks < 2; ks++) {
            const int cA = (ks * 16 + (lane >> 4) * 8) >> 3;
            const int cB = (ks * 16 + ((lane >> 3) & 1) * 8) >> 3;
            aA[ks] = rowA * 64 + ((cA ^ ((rowA >> 1) & 3)) << 4);
            aB[ks] = rowB * 64 + ((cB ^ ((rowB >> 1) & 3)) << 4);
        }
    }

    float acc[4][4][4];
    #pragma unroll
    for (int i = 0; i < 4; i++)
        #pragma unroll
        for (int j = 0; j < 4; j++)
            #pragma unroll
            for (int k = 0; k < 4; k++) acc[i][j][k] = 0.f;

    const int NC = K >> 5;

    // chunk loader: 256 threads x 2 iters x 4 matrices x 16B
    auto load_chunk = [&](uint32_t sbuf, int k0) {
        #pragma unroll
        for (int t = 0; t < 2; t++) {
            const int idx = tid + t * 256;        // 0..511
            const int r = idx >> 2, c = idx & 3;
            const uint32_t so = r * 64 + ((c ^ ((r >> 1) & 3)) << 4);
            const size_t ga = (size_t)(mBase + r) * K + k0 + c * 8;
            const size_t gw = (size_t)(nBase + r) * K + k0 + c * 8;
            cp_async16(sbuf + so,         Ahi + ga);
            cp_async16(sbuf + 8192 + so,  Alo + ga);
            cp_async16(sbuf + 16384 + so, Whi + gw);
            cp_async16(sbuf + 24576 + so, Wlo + gw);
        }
    };

    load_chunk(sbase, 0);
    cp_commit();

    for (int kc = 0; kc < NC; kc++) {
        const uint32_t cbuf = sbase + (kc & 1) * 32768;
        if (kc + 1 < NC) {
            load_chunk(sbase + ((kc + 1) & 1) * 32768, (kc + 1) * 32);
            cp_commit();
            cp_wait<1>();
        } else {
            cp_wait<0>();
        }
        __syncthreads();

        #pragma unroll
        for (int ks = 0; ks < 2; ks++) {
            uint32_t Ah[4][4], Al[4][4], Bh[4][2], Bl[4][2];
            #pragma unroll
            for (int mt = 0; mt < 4; mt++) {
                ldmx4(Ah[mt], cbuf + aA[ks] + mt * 1024);
                ldmx4(Al[mt], cbuf + 8192 + aA[ks] + mt * 1024);
            }
            #pragma unroll
            for (int nt = 0; nt < 4; nt++) {
                ldmx2(Bh[nt], cbuf + 16384 + aB[ks] + nt * 512);
                ldmx2(Bl[nt], cbuf + 24576 + aB[ks] + nt * 512);
            }
            #pragma unroll
            for (int mt = 0; mt < 4; mt++)
                #pragma unroll
                for (int nt = 0; nt < 4; nt++) {
                    mma_bf16(acc[mt][nt], Ah[mt], Bh[nt]);
                    mma_bf16(acc[mt][nt], Ah[mt], Bl[nt]);
                    mma_bf16(acc[mt][nt], Al[mt], Bh[nt]);
                }
        }
        __syncthreads();
    }

    // epilogue
    const int r0 = mBase + wm * 64 + (lane >> 2);
    const int c0 = nBase + wn * 32 + (lane & 3) * 2;
    #pragma unroll
    for (int mt = 0; mt < 4; mt++) {
        #pragma unroll
        for (int nt = 0; nt < 4; nt++) {
            const int r = r0 + mt * 16;
            const int c = c0 + nt * 8;
            const float b0 = __ldg(bias + c), b1 = __ldg(bias + c + 1);
            if (OUT == 2) {
                float v0 = fmaxf(acc[mt][nt][0] + b0, 0.f);
                float v1 = fmaxf(acc[mt][nt][1] + b1, 0.f);
                float v2 = fmaxf(acc[mt][nt][2] + b0, 0.f);
                float v3 = fmaxf(acc[mt][nt][3] + b1, 0.f);
                bf16 h0 = __float2bfloat16(v0), h1 = __float2bfloat16(v1);
                bf16 h2 = __float2bfloat16(v2), h3 = __float2bfloat16(v3);
                *(__nv_bfloat162*)(Chi + (size_t)r * N + c) = __nv_bfloat162(h0, h1);
                *(__nv_bfloat162*)(Chi + (size_t)(r + 8) * N + c) = __nv_bfloat162(h2, h3);
                *(__nv_bfloat162*)(Clo + (size_t)r * N + c) =
                    __nv_bfloat162(__float2bfloat16(v0 - __bfloat162float(h0)),
                                   __float2bfloat16(v1 - __bfloat162float(h1)));
                *(__nv_bfloat162*)(Clo + (size_t)(r + 8) * N + c) =
                    __nv_bfloat162(__float2bfloat16(v2 - __bfloat162float(h2)),
                                   __float2bfloat16(v3 - __bfloat162float(h3)));
            } else {
                float2 o0 = make_float2(acc[mt][nt][0] + b0, acc[mt][nt][1] + b1);
                float2 o1 = make_float2(acc[mt][nt][2] + b0, acc[mt][nt][3] + b1);
                *(float2*)(C + (size_t)r * N + c) = o0;
                *(float2*)(C + (size_t)(r + 8) * N + c) = o1;
            }
        }
    }
}

// ---------------- fused attention (flash-style, one block per (b,h)) ----------
__global__ __launch_bounds__(256, 1)
void attention_kernel(const float* __restrict__ QKV,
                      bf16* __restrict__ Ohi, bf16* __restrict__ Olo) {
    extern __shared__ float sm[];
    float* Ks = sm;                 // [256][64]
    float* Vs = sm + SEQ * DHEAD;   // [256][64]
    const int h = blockIdx.x;
    const int b = blockIdx.y;
    const int tid = threadIdx.x;
    const size_t base = (size_t)b * SEQ * 1536;

    for (int idx = tid; idx < SEQ * DHEAD; idx += 256) {
        const int j = idx >> 6, d = idx & 63;
        const size_t rb = base + (size_t)j * 1536 + h * DHEAD + d;
        Ks[idx] = QKV[rb + 512];
        Vs[idx] = QKV[rb + 1024];
    }
    __syncthreads();

    unsigned long long q2[32];
    {
        const float* qp = QKV + base + (size_t)tid * 1536 + h * DHEAD;
        #pragma unroll
        for (int i = 0; i < 32; i++) q2[i] = pack2(qp[2 * i], qp[2 * i + 1]);
    }
    unsigned long long acc[32];
    #pragma unroll
    for (int i = 0; i < 32; i++) acc[i] = 0ULL;

    float m = -1e30f, lsum = 0.f;
    const unsigned long long* Ku = (const unsigned long long*)Ks;
    const unsigned long long* Vu = (const unsigned long long*)Vs;

    for (int j = 0; j < SEQ; j++) {
        // 4 independent chains to break the RAW latency wall
        unsigned long long d0 = 0ULL, d1 = 0ULL, d2 = 0ULL, d3 = 0ULL;
        #pragma unroll
        for (int i = 0; i < 32; i += 4) {
            fma2(d0, q2[i],     Ku[j * 32 + i]);
            fma2(d1, q2[i + 1], Ku[j * 32 + i + 1]);
            fma2(d2, q2[i + 2], Ku[j * 32 + i + 2]);
            fma2(d3, q2[i + 3], Ku[j * 32 + i + 3]);
        }
        float2 p0 = unpack2(d0), p1 = unpack2(d1), p2v = unpack2(d2), p3 = unpack2(d3);
        const float sc = ((p0.x + p0.y) + (p1.x + p1.y) + (p2v.x + p2v.y) + (p3.x + p3.y)) * 0.125f;
        if (sc > m) {
            const float corr = __expf(m - sc);
            lsum *= corr;
            unsigned long long c2 = pack2(corr, corr);
            #pragma unroll
            for (int i = 0; i < 32; i++) mul2(acc[i], c2);
            m = sc;
        }
        const float p = __expf(sc - m);
        lsum += p;
        unsigned long long pp = pack2(p, p);
        #pragma unroll
        for (int i = 0; i < 32; i++) fma2(acc[i], pp, Vu[j * 32 + i]);
    }

    const float invl = 1.f / lsum;
    const size_t ob = ((size_t)b * SEQ + tid) * DMODEL + h * DHEAD;
    #pragma unroll
    for (int i = 0; i < 32; i++) {
        float2 v = unpack2(acc[i]);
        const float v0 = v.x * invl, v1 = v.y * invl;
        const bf16 h0 = __float2bfloat16(v0), h1 = __float2bfloat16(v1);
        Ohi[ob + 2 * i]     = h0;
        Ohi[ob + 2 * i + 1] = h1;
        Olo[ob + 2 * i]     = __float2bfloat16(v0 - __bfloat162float(h0));
        Olo[ob + 2 * i + 1] = __float2bfloat16(v1 - __bfloat162float(h1));
    }
}

// ---------------- residual add + LayerNorm (+ hi/lo split) -------------------
__global__ void add_ln_kernel(float* __restrict__ X, const float* __restrict__ R,
                              const float* __restrict__ gamma, const float* __restrict__ beta,
                              bf16* __restrict__ Xhi, bf16* __restrict__ Xlo) {
    const int t = blockIdx.x;
    const int tid = threadIdx.x;    // 256
    const size_t o = (size_t)t * DMODEL;
    const float y0 = X[o + tid] + R[o + tid];
    const float y1 = X[o + tid + 256] + R[o + tid + 256];
    float s  = y0 + y1;
    float sq = y0 * y0 + y1 * y1;

    __shared__ float sS[8], sQ[8];
    const float ws = warpSum(s), wq = warpSum(sq);
    const int w = tid >> 5, ln = tid & 31;
    if (ln == 0) { sS[w] = ws; sQ[w] = wq; }
    __syncthreads();
    float tS = 0.f, tQ = 0.f;
    #pragma unroll
    for (int i = 0; i < 8; i++) { tS += sS[i]; tQ += sQ[i]; }
    const float mean = tS * (1.f / DMODEL);
    const float var  = tQ * (1.f / DMODEL) - mean * mean;
    const float inv  = rsqrtf(var + 1e-5f);
    const float z0 = (y0 - mean) * inv * gamma[tid]       + beta[tid];
    const float z1 = (y1 - mean) * inv * gamma[tid + 256] + beta[tid + 256];
    X[o + tid]       = z0;
    X[o + tid + 256] = z1;
    const bf16 h0 = __float2bfloat16(z0), h1 = __float2bfloat16(z1);
    Xhi[o + tid]       = h0;
    Xhi[o + tid + 256] = h1;
    Xlo[o + tid]       = __float2bfloat16(z0 - __bfloat162float(h0));
    Xlo[o + tid + 256] = __float2bfloat16(z1 - __bfloat162float(h1));
}

// ---------------- latent GEMM split-K (fp32, f32x2) --------------------------
__global__ __launch_bounds__(256, 2)
void latent_partial(const float* __restrict__ Xf, const float* __restrict__ Wl,
                    float* __restrict__ P) {
    __shared__ float As[16][64];
    __shared__ float Ws[16][64];
    const int tid = threadIdx.x;
    const int tx = tid & 15, ty = tid >> 4;
    const int nBase = blockIdx.x * 64;
    const int kBase = blockIdx.y * 2048;
    const int lr = tid >> 2;
    const int lk = (tid & 3) * 4;

    unsigned long long acc[4][2];
    #pragma unroll
    for (int i = 0; i < 4; i++) { acc[i][0] = 0ULL; acc[i][1] = 0ULL; }

    const float* Ab = Xf + (size_t)lr * SD + kBase;
    const float* Wb = Wl + (size_t)(nBase + lr) * SD + kBase;

    for (int k0 = 0; k0 < 2048; k0 += 16) {
        float4 a = *(const float4*)(Ab + k0 + lk);
        float4 w = *(const float4*)(Wb + k0 + lk);
        __syncthreads();
        As[lk + 0][lr] = a.x; As[lk + 1][lr] = a.y; As[lk + 2][lr] = a.z; As[lk + 3][lr] = a.w;
        Ws[lk + 0][lr] = w.x; Ws[lk + 1][lr] = w.y; Ws[lk + 2][lr] = w.z; Ws[lk + 3][lr] = w.w;
        __syncthreads();
        #pragma unroll
        for (int kk = 0; kk < 16; kk++) {
            float a4[4];
            #pragma unroll
            for (int i = 0; i < 4; i++) a4[i] = As[kk][ty * 4 + i];
            const unsigned long long* wrow = (const unsigned long long*)&Ws[kk][0];
            unsigned long long w2[2] = { wrow[tx * 2], wrow[tx * 2 + 1] };
            #pragma unroll
            for (int i = 0; i < 4; i++) {
                unsigned long long ad = pack2(a4[i], a4[i]);
                fma2(acc[i][0], ad, w2[0]);
                fma2(acc[i][1], ad, w2[1]);
            }
        }
    }
    #pragma unroll
    for (int i = 0; i < 4; i++) {
        const int bb = ty * 4 + i;
        #pragma unroll
        for (int j = 0; j < 2; j++) {
            float2 v = unpack2(acc[i][j]);
            const int n = nBase + tx * 4 + 2 * j;
            P[(size_t)blockIdx.y * (BATCH * DLAT) + bb * DLAT + n]     = v.x;
            P[(size_t)blockIdx.y * (BATCH * DLAT) + bb * DLAT + n + 1] = v.y;
        }
    }
}

__global__ void latent_reduce(const float* __restrict__ P, const float* __restrict__ lb,
                              float* __restrict__ mem) {
    const int idx = blockIdx.x * 256 + threadIdx.x;  // 16384
    float s = lb[idx & (DLAT - 1)];
    #pragma unroll 8
    for (int ks = 0; ks < 64; ks++) s += P[(size_t)ks * (BATCH * DLAT) + idx];
    mem[idx] = s;
}

__global__ void head_kernel(const float* __restrict__ mem, const float* __restrict__ hw,
                            const float* __restrict__ hb, float* __restrict__ out) {
    const int b = blockIdx.x;
    const int tid = threadIdx.x;  // 256
    float v = mem[b * DLAT + tid] * hw[tid];
    __shared__ float sS[8];
    const float ws = warpSum(v);
    if ((tid & 31) == 0) sS[tid >> 5] = ws;
    __syncthreads();
    if (tid == 0) {
        float t = 0.f;
        #pragma unroll
        for (int i = 0; i < 8; i++) t += sS[i];
        const float z = t + hb[0];
        out[b] = 1.f / (1.f + expf(-z));
    }
}

// ---------------- launch ----------------
#define GEMM_SMEM (2 * 32768)

extern "C" void kernel_launch(void* const* d_in, const int* in_sizes, int n_in,
                              void* d_out, int out_size) {
    const float* src    = (const float*)d_in[0];
    const float* emb_w  = (const float*)d_in[1];
    const float* emb_b  = (const float*)d_in[2];
    const float* qkv_w  = (const float*)d_in[3];
    const float* qkv_b  = (const float*)d_in[4];
    const float* out_w  = (const float*)d_in[5];
    const float* out_b  = (const float*)d_in[6];
    const float* ff1_w  = (const float*)d_in[7];
    const float* ff1_b  = (const float*)d_in[8];
    const float* ff2_w  = (const float*)d_in[9];
    const float* ff2_b  = (const float*)d_in[10];
    const float* ln1_g  = (const float*)d_in[11];
    const float* ln1_b  = (const float*)d_in[12];
    const float* ln2_g  = (const float*)d_in[13];
    const float* ln2_b  = (const float*)d_in[14];
    const float* lat_w  = (const float*)d_in[15];
    const float* lat_b  = (const float*)d_in[16];
    const float* head_w = (const float*)d_in[17];
    const float* head_b = (const float*)d_in[18];
    float* out = (float*)d_out;

    float *X, *QKV, *Tb, *P, *MEM;
    bf16 *Xhi, *Xlo, *Ohi, *Olo, *Hhi, *Hlo;
    bf16 *Wqh, *Wql, *Woh, *Wol, *W1h, *W1l, *W2h, *W2l;
    cudaGetSymbolAddress((void**)&X,   g_X);
    cudaGetSymbolAddress((void**)&QKV, g_QKV);
    cudaGetSymbolAddress((void**)&Tb,  g_T);
    cudaGetSymbolAddress((void**)&P,   g_LP);
    cudaGetSymbolAddress((void**)&MEM, g_MEM);
    cudaGetSymbolAddress((void**)&Xhi, g_Xhi);
    cudaGetSymbolAddress((void**)&Xlo, g_Xlo);
    cudaGetSymbolAddress((void**)&Ohi, g_Ohi);
    cudaGetSymbolAddress((void**)&Olo, g_Olo);
    cudaGetSymbolAddress((void**)&Hhi, g_Hhi);
    cudaGetSymbolAddress((void**)&Hlo, g_Hlo);
    cudaGetSymbolAddress((void**)&Wqh, g_Wqh);
    cudaGetSymbolAddress((void**)&Wql, g_Wql);
    cudaGetSymbolAddress((void**)&Woh, g_Woh);
    cudaGetSymbolAddress((void**)&Wol, g_Wol);
    cudaGetSymbolAddress((void**)&W1h, g_W1h);
    cudaGetSymbolAddress((void**)&W1l, g_W1l);
    cudaGetSymbolAddress((void**)&W2h, g_W2h);
    cudaGetSymbolAddress((void**)&W2l, g_W2l);

    cudaFuncSetAttribute(attention_kernel,
                         cudaFuncAttributeMaxDynamicSharedMemorySize, 131072);
    cudaFuncSetAttribute(gemm_tc<0>,
                         cudaFuncAttributeMaxDynamicSharedMemorySize, GEMM_SMEM);
    cudaFuncSetAttribute(gemm_tc<2>,
                         cudaFuncAttributeMaxDynamicSharedMemorySize, GEMM_SMEM);

    // one-time-per-call weight splits
    {
        const int nq = NLAYER * 3 * DMODEL * DMODEL;
        const int no = NLAYER * DMODEL * DMODEL;
        const int n1 = NLAYER * DFF * DMODEL;
        const int n2 = NLAYER * DMODEL * DFF;
        split_kernel<<<(nq + 255) / 256, 256>>>(qkv_w, Wqh, Wql, nq);
        split_kernel<<<(no + 255) / 256, 256>>>(out_w, Woh, Wol, no);
        split_kernel<<<(n1 + 255) / 256, 256>>>(ff1_w, W1h, W1l, n1);
        split_kernel<<<(n2 + 255) / 256, 256>>>(ff2_w, W2h, W2l, n2);
    }

    embed_kernel<<<NTOK, 128>>>(src, emb_w, emb_b, X, Xhi, Xlo);

    for (int l = 0; l < NLAYER; l++) {
        gemm_tc<0><<<dim3(12, 128), 256, GEMM_SMEM>>>(
            Xhi, Xlo, Wqh + (size_t)l * 1536 * DMODEL, Wql + (size_t)l * 1536 * DMODEL,
            qkv_b + l * 1536, QKV, nullptr, nullptr, NTOK, 1536, DMODEL);
        attention_kernel<<<dim3(NHEAD, BATCH), 256, 131072>>>(QKV, Ohi, Olo);
        gemm_tc<0><<<dim3(4, 128), 256, GEMM_SMEM>>>(
            Ohi, Olo, Woh + (size_t)l * DMODEL * DMODEL, Wol + (size_t)l * DMODEL * DMODEL,
            out_b + l * DMODEL, Tb, nullptr, nullptr, NTOK, DMODEL, DMODEL);
        add_ln_kernel<<<NTOK, 256>>>(X, Tb, ln1_g + l * DMODEL, ln1_b + l * DMODEL, Xhi, Xlo);
        gemm_tc<2><<<dim3(16, 128), 256, GEMM_SMEM>>>(
            Xhi, Xlo, W1h + (size_t)l * DFF * DMODEL, W1l + (size_t)l * DFF * DMODEL,
            ff1_b + l * DFF, nullptr, Hhi, Hlo, NTOK, DFF, DMODEL);
        gemm_tc<0><<<dim3(4, 128), 256, GEMM_SMEM>>>(
            Hhi, Hlo, W2h + (size_t)l * DMODEL * DFF, W2l + (size_t)l * DMODEL * DFF,
            ff2_b + l * DMODEL, Tb, nullptr, nullptr, NTOK, DMODEL, DFF);
        add_ln_kernel<<<NTOK, 256>>>(X, Tb, ln2_g + l * DMODEL, ln2_b + l * DMODEL, Xhi, Xlo);
    }

    latent_partial<<<dim3(4, 64), 256>>>(X, lat_w, P);
    latent_reduce<<<64, 256>>>(P, lat_b, MEM);
    head_kernel<<<BATCH, 256>>>(MEM, head_w, head_b, out);
}